// round 4
// baseline (speedup 1.0000x reference)
#include <cuda_runtime.h>
#include <cuda_bf16.h>
#include <math.h>

// Problem dims
#define TT 512
#define BB 64
#define II 512
#define HH 512

// ---------------- device scratch ----------------
__device__ float g_xz[TT * BB];   // [t][b] includes zt_w_b
__device__ float g_xr[TT * BB];   // [t][b] includes rt_w_b

// ---------------- helpers ----------------
typedef unsigned long long ull;
union U64F2 { ull u; float2 f; };
union QU    { uint4 q; ull u[2]; };

__device__ __forceinline__ void fma2(ull& d, ull a, ull b) {
    asm("fma.rn.f32x2 %0, %1, %2, %0;" : "+l"(d) : "l"(a), "l"(b));
}
__device__ __forceinline__ ull pack2(float lo, float hi) {
    ull r; asm("mov.b64 %0, {%1, %2};" : "=l"(r) : "f"(lo), "f"(hi)); return r;
}
__device__ __forceinline__ float sigmoid_fast(float x) {
    float e, r;
    asm("ex2.approx.f32 %0, %1;" : "=f"(e) : "f"(-1.4426950408889634f * x));
    asm("rcp.approx.f32 %0, %1;" : "=f"(r) : "f"(1.0f + e));
    return r;
}
__device__ __forceinline__ float tanh_fast(float x) {
    // tanh(x) = 2*sigmoid(2x) - 1
    float e, r;
    asm("ex2.approx.f32 %0, %1;" : "=f"(e) : "f"(-2.8853900817779268f * x));
    asm("rcp.approx.f32 %0, %1;" : "=f"(r) : "f"(1.0f + e));
    return fmaf(2.0f, r, -1.0f);
}
__device__ __forceinline__ unsigned smem_u32(const void* p) {
    return (unsigned)__cvta_generic_to_shared(p);
}

// ---------------- kernel 1: gate input projections xz, xr ----------------
__global__ void gate_pre_kernel(const float* __restrict__ in,
                                const float* __restrict__ zw, const float* __restrict__ zb,
                                const float* __restrict__ rw, const float* __restrict__ rb) {
    int row  = blockIdx.x * 8 + (threadIdx.x >> 5);
    int lane = threadIdx.x & 31;
    const float4* a4 = (const float4*)(in + (size_t)row * II);
    const float4* z4 = (const float4*)zw;
    const float4* r4 = (const float4*)rw;
    float az = 0.f, ar = 0.f;
#pragma unroll 4
    for (int i = lane; i < II / 4; i += 32) {
        float4 v = a4[i];
        float4 z = z4[i];
        float4 r = r4[i];
        az += v.x * z.x + v.y * z.y + v.z * z.z + v.w * z.w;
        ar += v.x * r.x + v.y * r.y + v.z * r.z + v.w * r.w;
    }
#pragma unroll
    for (int off = 16; off >= 1; off >>= 1) {
        az += __shfl_xor_sync(0xffffffffu, az, off);
        ar += __shfl_xor_sync(0xffffffffu, ar, off);
    }
    if (lane == 0) {
        g_xz[row] = az + zb[0];
        g_xr[row] = ar + rb[0];
    }
}

// ---------------- kernel 2: xn GEMM, k-pair f32x2, no MOVs in mainloop ----
// C[m][n] = sum_k A[m,k] W[n,k] + bias[n].  M=32768, N=512, K=512.
// BM=128, BN=64, BK=32 (16 k-pairs). 256 threads: ncol=tid&7 (8n each), mrow=tid>>3 (4m each).
__global__ __launch_bounds__(256) void xn_gemm_kernel(const float* __restrict__ A,
                                                      const float* __restrict__ W,
                                                      const float* __restrict__ bias,
                                                      float* __restrict__ C) {
    __shared__ ull As2[16][130];   // [kp][m], pad 2 for bank spread
    __shared__ ull Ws2[16][66];    // [kp][n]

    int tid  = threadIdx.x;
    int ncol = tid & 7;
    int mrow = tid >> 3;
    int bm   = blockIdx.x * 128;
    int bn   = blockIdx.y * 64;

    ull acc[4][8];
#pragma unroll
    for (int i = 0; i < 4; i++)
#pragma unroll
        for (int j = 0; j < 8; j++) acc[i][j] = 0ull;

    const float4* A4 = (const float4*)A;
    const float4* W4 = (const float4*)W;

    float4 pa[4], pw[2];
    // preload block 0
#pragma unroll
    for (int q = 0; q < 4; q++) {
        int s = tid + q * 256;
        pa[q] = A4[(size_t)(bm + (s >> 3)) * 128 + (s & 7)];
    }
#pragma unroll
    for (int q = 0; q < 2; q++) {
        int s = tid + q * 256;
        pw[q] = W4[(size_t)(bn + (s >> 3)) * 128 + (s & 7)];
    }

    for (int blk = 0; blk < 16; blk++) {
        // store current tiles
#pragma unroll
        for (int q = 0; q < 4; q++) {
            int s = tid + q * 256;
            int m = s >> 3, f4 = s & 7;
            As2[f4 * 2][m]     = pack2(pa[q].x, pa[q].y);
            As2[f4 * 2 + 1][m] = pack2(pa[q].z, pa[q].w);
        }
#pragma unroll
        for (int q = 0; q < 2; q++) {
            int s = tid + q * 256;
            int n = s >> 3, f4 = s & 7;
            Ws2[f4 * 2][n]     = pack2(pw[q].x, pw[q].y);
            Ws2[f4 * 2 + 1][n] = pack2(pw[q].z, pw[q].w);
        }
        __syncthreads();
        // prefetch next
        if (blk < 15) {
            int kq = (blk + 1) * 8;
#pragma unroll
            for (int q = 0; q < 4; q++) {
                int s = tid + q * 256;
                pa[q] = A4[(size_t)(bm + (s >> 3)) * 128 + kq + (s & 7)];
            }
#pragma unroll
            for (int q = 0; q < 2; q++) {
                int s = tid + q * 256;
                pw[q] = W4[(size_t)(bn + (s >> 3)) * 128 + kq + (s & 7)];
            }
        }
        // compute
#pragma unroll
        for (int kp = 0; kp < 16; kp++) {
            QU a01, a23, w01, w23, w45, w67;
            a01.q = *(const uint4*)&As2[kp][mrow * 4];
            a23.q = *(const uint4*)&As2[kp][mrow * 4 + 2];
            w01.q = *(const uint4*)&Ws2[kp][ncol * 8];
            w23.q = *(const uint4*)&Ws2[kp][ncol * 8 + 2];
            w45.q = *(const uint4*)&Ws2[kp][ncol * 8 + 4];
            w67.q = *(const uint4*)&Ws2[kp][ncol * 8 + 6];
            ull av[4] = {a01.u[0], a01.u[1], a23.u[0], a23.u[1]};
            ull wv[8] = {w01.u[0], w01.u[1], w23.u[0], w23.u[1],
                         w45.u[0], w45.u[1], w67.u[0], w67.u[1]};
#pragma unroll
            for (int i = 0; i < 4; i++)
#pragma unroll
                for (int j = 0; j < 8; j++) fma2(acc[i][j], av[i], wv[j]);
        }
        __syncthreads();
    }

    float4 b0 = ((const float4*)bias)[(bn >> 2) + ncol * 2];
    float4 b1 = ((const float4*)bias)[(bn >> 2) + ncol * 2 + 1];
#pragma unroll
    for (int mi = 0; mi < 4; mi++) {
        int m = bm + mrow * 4 + mi;
        U64F2 c[8];
#pragma unroll
        for (int j = 0; j < 8; j++) c[j].u = acc[mi][j];
        float4 o0, o1;
        o0.x = c[0].f.x + c[0].f.y + b0.x;
        o0.y = c[1].f.x + c[1].f.y + b0.y;
        o0.z = c[2].f.x + c[2].f.y + b0.z;
        o0.w = c[3].f.x + c[3].f.y + b0.w;
        o1.x = c[4].f.x + c[4].f.y + b1.x;
        o1.y = c[5].f.x + c[5].f.y + b1.y;
        o1.z = c[6].f.x + c[6].f.y + b1.z;
        o1.w = c[7].f.x + c[7].f.y + b1.w;
        ((float4*)C)[(size_t)m * 128 + (bn >> 2) + ncol * 2]     = o0;
        ((float4*)C)[(size_t)m * 128 + (bn >> 2) + ncol * 2 + 1] = o1;
    }
}

// ---------------- kernel 3: recurrent scan ----------------
// 16 clusters x 8 CTAs x 512 threads. Cluster g -> batches 4g..4g+3.
// CTA rank r -> h outputs [64r,64r+64). h exchanged via st.async + mbarrier
// expect_tx/complete_tx (double-buffered); no cluster barrier in the loop.
// All packed data uses k-pair f32x2 layout: ull = (even-k val, odd-k val).
#define WS_OFF   0                        // ull[256][64]  = 128KB  wS[kp*64+jj]
#define HP_OFF   131072                   // ull[2][1024]  = 16KB   hp[s][kp*4+b]
#define PART_OFF (HP_OFF + 16384)         // float[16][4][64] = 16KB
#define ZRP_OFF  (PART_OFF + 16384)       // float[64] (float4[gate*8+ks8])
#define ZUP_OFF  (ZRP_OFF + 256)          // ull[256]
#define RUP_OFF  (ZUP_OFF + 2048)         // ull[256]
#define HUB_OFF  (RUP_OFF + 2048)         // float[64]
#define MBAR_OFF (HUB_OFF + 256)          // 2 x b64
#define SC_SMEM  (MBAR_OFF + 64)

extern __shared__ char sc_smem[];

__global__ void __cluster_dims__(8, 1, 1) __launch_bounds__(512, 1)
scan_kernel(const float* __restrict__ hidden,
            const float* __restrict__ ztu_g, const float* __restrict__ ztub,
            const float* __restrict__ rtu_g, const float* __restrict__ rtub,
            const float* __restrict__ huw, const float* __restrict__ hub_g,
            float* __restrict__ out, int tail) {
    ull*   wS   = (ull*)(sc_smem + WS_OFF);
    ull*   hpb  = (ull*)(sc_smem + HP_OFF);
    float* part = (float*)(sc_smem + PART_OFF);
    float* zrpf = (float*)(sc_smem + ZRP_OFF);
    ull*   zup  = (ull*)(sc_smem + ZUP_OFF);
    ull*   rup  = (ull*)(sc_smem + RUP_OFF);
    float* hub  = (float*)(sc_smem + HUB_OFF);

    int tid    = threadIdx.x;
    int rank   = blockIdx.x & 7;
    int grp    = blockIdx.x >> 3;
    int jjbase = rank * 64;
    unsigned mbase = smem_u32(sc_smem + MBAR_OFF);

    // -------- prologue --------
    for (int i = tid; i < 64 * 512; i += 512) {
        int jj = i >> 9, k = i & 511;
        ((float*)wS)[((k >> 1) * 64 + jj) * 2 + (k & 1)] = huw[(size_t)(jjbase + jj) * HH + k];
    }
    if (tid < 256) zup[tid] = ((const ull*)ztu_g)[tid];
    else           rup[tid - 256] = ((const ull*)rtu_g)[tid - 256];
    for (int i = tid; i < 1024; i += 512) {
        hpb[i] = ((const ull*)hidden)[(size_t)(grp * 4 + (i & 3)) * 256 + (i >> 2)];
    }
    if (tid < 64) hub[tid] = hub_g[jjbase + tid];
    float zub = ztub[0], rub = rtub[0];
    if (tid == 0) {
        asm volatile("mbarrier.init.shared.b64 [%0], %1;" :: "r"(mbase), "r"(1) : "memory");
        asm volatile("mbarrier.init.shared.b64 [%0], %1;" :: "r"(mbase + 8), "r"(1) : "memory");
    }
    __syncthreads();
    asm volatile("barrier.cluster.arrive.aligned;" ::: "memory");
    asm volatile("barrier.cluster.wait.aligned;" ::: "memory");

    int lane = tid & 31;
    int warp = tid >> 5;
    int jjp  = lane;            // jj pair index 0..31
    int ks   = warp;            // k segment 0..15 (16 kp each)
    int gate = warp & 1;
    int ks8  = warp >> 1;
    int jj4  = tid & 63;
    int b4   = (tid >> 6) & 3;

    int par0 = 0, par1 = 0;

    for (int t = 0; t < TT; t++) {
        int s = t & 1, sf = s ^ 1;
        unsigned mb_s  = mbase + s * 8;
        unsigned mb_sf = mbase + sf * 8;

        if (tid == 0 && t < TT - 1) {
            asm volatile("mbarrier.arrive.expect_tx.shared::cta.b64 _, [%0], %1;"
                         :: "r"(mb_sf), "r"(8192) : "memory");
        }
        if (t > 0) {
            int ph = s ? par1 : par0;
            unsigned done = 0;
            while (!done) {
                asm volatile(
                    "{\n\t.reg .pred p;\n\t"
                    "mbarrier.try_wait.parity.acquire.cta.shared::cta.b64 p, [%1], %2, 0x989680;\n\t"
                    "selp.b32 %0, 1, 0, p;\n\t}"
                    : "=r"(done) : "r"(mb_s), "r"(ph) : "memory");
            }
            if (s) par1 ^= 1; else par0 ^= 1;
        }

        const ull* hp = hpb + s * 1024;

        // early global prefetch (independent of h)
        size_t obase = 0;
        float xnv = 0.f, xzv = 0.f, xrv = 0.f;
        if (tid < 256) {
            obase = (size_t)t * BB * HH + (size_t)(grp * 4 + b4) * HH + jjbase + jj4;
            xnv = out[obase];
            xzv = g_xz[t * BB + grp * 4 + b4];
            xrv = g_xr[t * BB + grp * 4 + b4];
        }

        // -------- gates: 16 warps = gate(2) x ks8(8), 64 k (32 kp) each --------
        {
            int kp = ks8 * 32 + lane;
            ull u = (gate ? rup : zup)[kp];
            QU A, B;
            A.q = *(const uint4*)(hp + kp * 4);
            B.q = *(const uint4*)(hp + kp * 4 + 2);
            ull a0 = 0, a1 = 0, a2 = 0, a3 = 0;
            fma2(a0, A.u[0], u);
            fma2(a1, A.u[1], u);
            fma2(a2, B.u[0], u);
            fma2(a3, B.u[1], u);
            U64F2 c0, c1, c2, c3;
            c0.u = a0; c1.u = a1; c2.u = a2; c3.u = a3;
            float s0 = c0.f.x + c0.f.y, s1 = c1.f.x + c1.f.y;
            float s2 = c2.f.x + c2.f.y, s3 = c3.f.x + c3.f.y;
#pragma unroll
            for (int off = 16; off >= 1; off >>= 1) {
                s0 += __shfl_xor_sync(0xffffffffu, s0, off);
                s1 += __shfl_xor_sync(0xffffffffu, s1, off);
                s2 += __shfl_xor_sync(0xffffffffu, s2, off);
                s3 += __shfl_xor_sync(0xffffffffu, s3, off);
            }
            if (lane == 0) ((float4*)zrpf)[gate * 8 + ks8] = make_float4(s0, s1, s2, s3);
        }

        // -------- main dot: k-pair f32x2, 2 jj x 4 b per thread --------
        {
            const ull* wp = wS + ks * 1024 + jjp * 2;
            const ull* hq = hp + ks * 64;
            ull a00 = 0, a01v = 0, a02 = 0, a03 = 0;
            ull a10 = 0, a11v = 0, a12 = 0, a13 = 0;
#pragma unroll
            for (int i = 0; i < 16; i++) {
                QU Wq, Ha, Hb;
                Wq.q = *(const uint4*)(wp + i * 64);
                Ha.q = *(const uint4*)(hq + i * 4);
                Hb.q = *(const uint4*)(hq + i * 4 + 2);
                fma2(a00,  Wq.u[0], Ha.u[0]);
                fma2(a01v, Wq.u[0], Ha.u[1]);
                fma2(a02,  Wq.u[0], Hb.u[0]);
                fma2(a03,  Wq.u[0], Hb.u[1]);
                fma2(a10,  Wq.u[1], Ha.u[0]);
                fma2(a11v, Wq.u[1], Ha.u[1]);
                fma2(a12,  Wq.u[1], Hb.u[0]);
                fma2(a13,  Wq.u[1], Hb.u[1]);
            }
            U64F2 u0, u1;
            float2* pp = (float2*)part;
            u0.u = a00;  u1.u = a10;
            pp[ks * 128 + 0 * 32 + jjp] = make_float2(u0.f.x + u0.f.y, u1.f.x + u1.f.y);
            u0.u = a01v; u1.u = a11v;
            pp[ks * 128 + 1 * 32 + jjp] = make_float2(u0.f.x + u0.f.y, u1.f.x + u1.f.y);
            u0.u = a02;  u1.u = a12;
            pp[ks * 128 + 2 * 32 + jjp] = make_float2(u0.f.x + u0.f.y, u1.f.x + u1.f.y);
            u0.u = a03;  u1.u = a13;
            pp[ks * 128 + 3 * 32 + jjp] = make_float2(u0.f.x + u0.f.y, u1.f.x + u1.f.y);
        }
        __syncthreads();

        // -------- finish: reduce + gates + write + fan-out --------
        if (tid < 256) {
            float ssum = 0.f;
#pragma unroll
            for (int ki = 0; ki < 16; ki++) ssum += part[ki * 256 + b4 * 64 + jj4];
            float gz = 0.f, gr = 0.f;
#pragma unroll
            for (int k8 = 0; k8 < 8; k8++) {
                gz += zrpf[k8 * 4 + b4];
                gr += zrpf[32 + k8 * 4 + b4];
            }
            float zt = sigmoid_fast(xzv + gz + zub);
            float rt = sigmoid_fast(xrv + gr + rub);
            float nt = tanh_fast(fmaf(ssum + hub[jj4], rt, xnv));
            U64F2 hold2; hold2.u = hp[((jjbase + jj4) >> 1) * 4 + b4];
            float hold = (jj4 & 1) ? hold2.f.y : hold2.f.x;
            float hn = (1.f - zt) * nt + zt * hold;
            out[obase] = hn;
            if (t == TT - 1) {
                if (tail >= BB * HH)
                    out[(size_t)TT * BB * HH + (size_t)(grp * 4 + b4) * HH + jjbase + jj4] = hn;
            } else {
                float hn1 = __shfl_down_sync(0xffffffffu, hn, 1);
                if ((jj4 & 1) == 0) {
                    ull v = pack2(hn, hn1);
                    unsigned loc = smem_u32(&hpb[sf * 1024 + ((jjbase + jj4) >> 1) * 4 + b4]);
#pragma unroll
                    for (int r = 0; r < 8; r++) {
                        unsigned rdst, rmb;
                        asm("mapa.shared::cluster.u32 %0, %1, %2;" : "=r"(rdst) : "r"(loc), "r"(r));
                        asm("mapa.shared::cluster.u32 %0, %1, %2;" : "=r"(rmb) : "r"(mb_sf), "r"(r));
                        asm volatile(
                            "st.async.shared::cluster.mbarrier::complete_tx::bytes.b64 [%0], %1, [%2];"
                            :: "r"(rdst), "l"(v), "r"(rmb) : "memory");
                    }
                }
            }
        }
        __syncthreads();
    }
}

// ---------------- launch ----------------
extern "C" void kernel_launch(void* const* d_in, const int* in_sizes, int n_in,
                              void* d_out, int out_size) {
    const float* input  = (const float*)d_in[0];
    const float* hidden = (const float*)d_in[1];
    const float* zt_w_w = (const float*)d_in[2];
    const float* zt_w_b = (const float*)d_in[3];
    const float* zt_u_w = (const float*)d_in[4];
    const float* zt_u_b = (const float*)d_in[5];
    const float* rt_w_w = (const float*)d_in[6];
    const float* rt_w_b = (const float*)d_in[7];
    const float* rt_u_w = (const float*)d_in[8];
    const float* rt_u_b = (const float*)d_in[9];
    const float* h_w_w  = (const float*)d_in[10];
    const float* h_w_b  = (const float*)d_in[11];
    const float* h_u_w  = (const float*)d_in[12];
    const float* h_u_b  = (const float*)d_in[13];
    float* out = (float*)d_out;

    int tail = out_size - TT * BB * HH;

    gate_pre_kernel<<<TT * BB / 8, 256>>>(input, zt_w_w, zt_w_b, rt_w_w, rt_w_b);

    {
        dim3 grid(TT * BB / 128, HH / 64);
        xn_gemm_kernel<<<grid, 256>>>(input, h_w_w, h_w_b, out);
    }

    static int smem_set = 0;
    if (!smem_set) {
        cudaFuncSetAttribute(scan_kernel, cudaFuncAttributeMaxDynamicSharedMemorySize, SC_SMEM);
        smem_set = 1;
    }
    scan_kernel<<<128, 512, SC_SMEM>>>(hidden, zt_u_w, zt_u_b, rt_u_w, rt_u_b,
                                       h_u_w, h_u_b, out, tail);
}